// round 15
// baseline (speedup 1.0000x reference)
#include <cuda_runtime.h>
#include <math.h>

#define T_TOT   200000
#define T_PAD   200704
#define PADL    64
#define SROW    (PADL + T_PAD + 64)
#define OROW    SROW
#define HIDN    20
#define SUBX2   40
#define NE      500
#define NI      100
#define KLEN    104
#define NBAS    34

__device__ float g_syn  [SUBX2 * SROW];
__device__ float g_out1 [HIDN  * OROW];
__device__ float g_kern1[HIDN * SUBX2 * KLEN];
__device__ float g_kern4[HIDN * KLEN];
__device__ float g_out4 [T_TOT];
__device__ float g_th   [200064];
__device__ float g_g    [64];
__device__ float g_skd  [64];
__device__ float g_theta[1];
__device__ int   g_idx_e[NE];
__device__ int   g_idx_i[NI];
__device__ unsigned long long g_spk[3200];

__device__ __forceinline__ unsigned long long f2add(unsigned long long a, unsigned long long b) {
    unsigned long long c;
    asm("add.rn.f32x2 %0, %1, %2;" : "=l"(c) : "l"(a), "l"(b));
    return c;
}
__device__ __forceinline__ float lo32f(unsigned long long a) { return __uint_as_float((unsigned)a); }
__device__ __forceinline__ float hi32f(unsigned long long a) { return __uint_as_float((unsigned)(a >> 32)); }

// ---------------- K0: params ----------------
__global__ void k0_params(const float* __restrict__ Ce, const float* __restrict__ Ci,
                          const float* __restrict__ w1, const float* __restrict__ w4,
                          const float* __restrict__ Wh, const float* __restrict__ Th,
                          const float* __restrict__ Ws, const float* __restrict__ Tau) {
    __shared__ float sB[NBAS * KLEN];
    int tid = threadIdx.x;
    for (int i = tid; i < NBAS * KLEN; i += blockDim.x) {
        int b = i / KLEN, k = i % KLEN;
        float d = (float)k - 3.0f * (float)b;
        sB[i] = (k < 101) ? expf(-d * d / 3.0f) : 0.0f;
    }
    __syncthreads();
    int gt = blockIdx.x * blockDim.x + tid;
    int gs = gridDim.x * blockDim.x;

    for (int i = gt; i < HIDN * SUBX2 * KLEN; i += gs) {
        int k = i % KLEN, hs = i / KLEN;
        float acc = 0.f;
        if (k < 101) {
            const float* w = w1 + hs * NBAS;
            #pragma unroll
            for (int b = 0; b < NBAS; b++) acc = fmaf(w[b], sB[b * KLEN + k], acc);
        }
        g_kern1[i] = acc;
    }
    for (int i = gt; i < HIDN * KLEN; i += gs) {
        int k = i % KLEN, h = i / KLEN;
        float acc = 0.f;
        if (k < 101) {
            #pragma unroll
            for (int b = 0; b < NBAS; b++) acc = fmaf(w4[h * NBAS + b], sB[b * KLEN + k], acc);
        }
        g_kern4[i] = acc;
    }
    for (int d = gt; d < 64; d += gs) {
        float gv = 0.f, sv = 0.f;
        if (d >= 1 && d <= 50) {
            int kk = 50 - d;
            float a = 0.f;
            for (int i2 = 0; i2 < 18; i2++) {
                float dd = (float)kk - 3.0f * (float)i2;
                a = fmaf(Wh[i2], expf(-dd * dd / 3.0f), a);
            }
            gv = a;
            float tau2 = Tau[0] * Tau[0];
            float tt = (float)(d - 1) / tau2;
            sv = tt * expf(-tt) * Ws[0] * Ws[0];
        }
        g_g[d] = gv; g_skd[d] = sv;
    }
    if (gt == 0) g_theta[0] = Th[0];
    for (int e = gt; e < NE; e += gs) {
        int s = 0;
        for (int j = 0; j < 20; j++) if (Ce[j * NE + e] > 0.5f) s = j;
        g_idx_e[e] = s;
    }
    for (int e = gt; e < NI; e += gs) {
        int s = 0;
        for (int j = 0; j < 20; j++) if (Ci[j * NI + e] > 0.5f) s = j;
        g_idx_i[e] = 20 + s;
    }
    for (int i = gt; i < SUBX2 * PADL; i += gs) {
        int s = i / PADL, c = i % PADL;
        g_syn[s * SROW + c] = 0.f;
        g_syn[s * SROW + PADL + T_PAD + c] = 0.f;
    }
    for (int i = gt; i < HIDN * PADL; i += gs) {
        int h = i / PADL, c = i % PADL;
        g_out1[h * OROW + c] = 0.f;
        g_out1[h * OROW + PADL + T_PAD + c] = 0.f;
    }
}

// ---------------- K1: routing ----------------
#define K1_TT 128
__global__ void __launch_bounds__(256) k1_route(const float* __restrict__ Se,
                                                const float* __restrict__ Si) {
    __shared__ float acc[K1_TT][41];
    __shared__ int sIe[NE];
    __shared__ int sIi[NI];
    int tid = threadIdx.x;
    for (int i = tid; i < NE; i += 256) sIe[i] = g_idx_e[i];
    for (int i = tid; i < NI; i += 256) sIi[i] = g_idx_i[i];
    for (int i = tid; i < K1_TT * 41; i += 256) ((float*)acc)[i] = 0.f;
    __syncthreads();
    int t0 = blockIdx.x * K1_TT;
    for (int i = tid; i < K1_TT * NE; i += 256) {
        int tl = i / NE, e = i % NE;
        int t = t0 + tl;
        if (t < T_TOT) {
            float v = Se[(size_t)t * NE + e];
            if (v != 0.f) atomicAdd(&acc[tl][sIe[e]], v);
        }
    }
    for (int i = tid; i < K1_TT * NI; i += 256) {
        int tl = i / NI, e = i % NI;
        int t = t0 + tl;
        if (t < T_TOT) {
            float v = Si[(size_t)t * NI + e];
            if (v != 0.f) atomicAdd(&acc[tl][sIi[e]], v);
        }
    }
    __syncthreads();
    for (int i = tid; i < K1_TT * 40; i += 256) {
        int s = i / K1_TT, tl = i % K1_TT;
        g_syn[s * SROW + PADL + t0 + tl] = acc[tl][s];
    }
}

// ---------------- K2: conv1 + leaky relu ----------------
__global__ void __launch_bounds__(128) k2_conv1() {
    __shared__ __align__(16) float sSyn[8 * 616];
    __shared__ __align__(16) float sK[4 * 8 * KLEN];
    int tx  = threadIdx.x;
    int bT0 = blockIdx.x * 512;
    int hb  = blockIdx.y * 4;

    float acc[4][4];
    #pragma unroll
    for (int a = 0; a < 4; a++)
        #pragma unroll
        for (int b = 0; b < 4; b++) acc[a][b] = 0.f;

    #pragma unroll 1
    for (int sc = 0; sc < 5; sc++) {
        __syncthreads();
        for (int i = tx; i < 8 * 616; i += 128) {
            int ss = i / 616, c = i % 616;
            sSyn[i] = g_syn[(sc * 8 + ss) * SROW + PADL + bT0 - 50 + c];
        }
        for (int i = tx; i < 4 * 8 * KLEN; i += 128) {
            int hh = i / (8 * KLEN);
            int r = i % (8 * KLEN);
            int ss = r / KLEN, k = r % KLEN;
            sK[i] = g_kern1[((hb + hh) * SUBX2 + sc * 8 + ss) * KLEN + k];
        }
        __syncthreads();
        #pragma unroll 1
        for (int ss = 0; ss < 8; ss++) {
            const float* sp = sSyn + ss * 616 + 4 * tx;
            #pragma unroll
            for (int k4 = 0; k4 < 26; k4++) {
                float4 a = *(const float4*)(sp + 4 * k4);
                float4 b = *(const float4*)(sp + 4 * k4 + 4);
                #pragma unroll
                for (int hh = 0; hh < 4; hh++) {
                    float4 kv = *(const float4*)(sK + (hh * 8 + ss) * KLEN + 4 * k4);
                    acc[hh][0] = fmaf(a.x, kv.x, fmaf(a.y, kv.y, fmaf(a.z, kv.z, fmaf(a.w, kv.w, acc[hh][0]))));
                    acc[hh][1] = fmaf(a.y, kv.x, fmaf(a.z, kv.y, fmaf(a.w, kv.z, fmaf(b.x, kv.w, acc[hh][1]))));
                    acc[hh][2] = fmaf(a.z, kv.x, fmaf(a.w, kv.y, fmaf(b.x, kv.z, fmaf(b.y, kv.w, acc[hh][2]))));
                    acc[hh][3] = fmaf(a.w, kv.x, fmaf(b.x, kv.y, fmaf(b.y, kv.z, fmaf(b.z, kv.w, acc[hh][3]))));
                }
            }
        }
    }
    int gb = bT0 + 4 * tx;
    #pragma unroll
    for (int hh = 0; hh < 4; hh++)
        #pragma unroll
        for (int j = 0; j < 4; j++) {
            int t = gb + j;
            float v = acc[hh][j];
            v = v > 0.f ? v : 0.01f * v;
            g_out1[(hb + hh) * OROW + PADL + t] = (t < T_TOT) ? v : 0.f;
        }
}

// ---------------- K3: conv4 + thresholds ----------------
__global__ void __launch_bounds__(256) k3_conv4(const float* __restrict__ u) {
    __shared__ float s1[20 * 360];
    __shared__ float sk[20 * KLEN];
    int tx = threadIdx.x;
    int bT0 = blockIdx.x * 256;
    for (int i = tx; i < 20 * 360; i += 256) {
        int h = i / 360, c = i % 360;
        s1[i] = g_out1[h * OROW + PADL + bT0 - 50 + c];
    }
    for (int i = tx; i < 20 * KLEN; i += 256) sk[i] = g_kern4[i];
    __syncthreads();
    float acc0 = 0.f, acc1 = 0.f;
    #pragma unroll 1
    for (int h = 0; h < 20; h++) {
        const float* p  = s1 + h * 360 + tx;
        const float* kq = sk + h * KLEN;
        #pragma unroll
        for (int k = 0; k < 100; k += 2) {
            acc0 = fmaf(p[k],     kq[k],     acc0);
            acc1 = fmaf(p[k + 1], kq[k + 1], acc1);
        }
        acc0 = fmaf(p[100], kq[100], acc0);
    }
    float acc = acc0 + acc1;
    int t = bT0 + tx;
    if (t < T_TOT) {
        g_out4[t] = acc;
        float uu = u[t];
        g_th[t] = logf(uu / (1.f - uu)) - acc - g_theta[0];
    } else if (t < 200064) {
        g_th[t] = 1e30f;
    }
}

// ---------------- K4: sequential scan (pipelined LUT + speculative lag-1) ----------------
// Bit-identical numerics to the round-12 kernel:
//  - tree order per lane: ((a0+a1)+(a2+a3))+(a4+a5)  (a0 = newest byte)
//  - fixup order: Bv0 = fma(b49,G50, fma(b48,G49, tree)); Bv1 = fma(b48,G50, tree)
//  - step r: x_r = fma(s_{r-1},G1, rest_r) realized as select(rest_r+G1, rest_r, p_{r-1})
__global__ void __launch_bounds__(256) k4_scan() {
    __shared__ __align__(16) float4 sLUT[12 * 256];
    int tid = threadIdx.x;
    for (int idx = tid; idx < 12 * 256; idx += 256) {
        int grp = idx / (6 * 256);
        int rem = idx % (6 * 256);
        int B = rem / 256, v = rem % 256;
        float4 o = make_float4(0.f, 0.f, 0.f, 0.f);
        for (int i = 0; i < 8; i++)
            if (v & (1 << i)) {
                int d0 = 8 * B + i + 1 + 4 * grp;
                o.x += g_g[d0];
                o.y += g_g[d0 + 1];
                o.z += g_g[d0 + 2];
                o.w += g_g[d0 + 3];
            }
        sLUT[idx] = o;
    }
    __syncthreads();
    if (tid != 0) return;

    float Gv[8];
    #pragma unroll
    for (int i = 0; i < 8; i++) Gv[i] = g_g[i];
    const float G1 = Gv[1];
    float G49 = g_g[49], G50 = g_g[50];

    const ulonglong2* L = (const ulonglong2*)sLUT;

    unsigned long long M = 0ull, outw = 0ull;
    // 4-deep raw-threshold prefetch queue
    float4 q0lo = *(const float4*)(g_th + 0),  q0hi = *(const float4*)(g_th + 4);
    float4 q1lo = *(const float4*)(g_th + 8),  q1hi = *(const float4*)(g_th + 12);
    float4 q2lo = *(const float4*)(g_th + 16), q2hi = *(const float4*)(g_th + 20);
    float4 q3lo = *(const float4*)(g_th + 24), q3hi = *(const float4*)(g_th + 28);

    // Bv for batch 0: M=0 -> all LUT entries index 0 (zero) -> Bv = 0 (fixups zero too)
    float Bv0 = 0.f, Bv1 = 0.f, Bv2 = 0.f, Bv3 = 0.f;
    float Bv4 = 0.f, Bv5 = 0.f, Bv6 = 0.f, Bv7 = 0.f;

    for (int ib = 0; ib < 25000; ib++) {
        // ---- pre-stage for batch ib+1: bytes b1..b5 of next M = bytes b0..b4 of M ----
        unsigned nlo = (unsigned)M, nhi = (unsigned)(M >> 32);
        int n1 = nlo & 255, n2 = (nlo >> 8) & 255, n3 = (nlo >> 16) & 255, n4 = nlo >> 24;
        int n5 = nhi & 255;
        ulonglong2 A1 = L[1 * 256 + n1], A2 = L[2 * 256 + n2], A3 = L[3 * 256 + n3];
        ulonglong2 A4 = L[4 * 256 + n4], A5 = L[5 * 256 + n5];
        ulonglong2 C1 = L[7 * 256 + n1], C2 = L[8 * 256 + n2], C3 = L[9 * 256 + n3];
        ulonglong2 C4 = L[10 * 256 + n4], C5 = L[11 * 256 + n5];
        unsigned long long PAx = f2add(A2.x, A3.x), QAx = f2add(A4.x, A5.x);
        unsigned long long PAy = f2add(A2.y, A3.y), QAy = f2add(A4.y, A5.y);
        unsigned long long PCx = f2add(C2.x, C3.x), QCx = f2add(C4.x, C5.x);
        unsigned long long PCy = f2add(C2.y, C3.y), QCy = f2add(C4.y, C5.y);
        // fixup bits for next batch: bits 48,49 of (M<<8) = bits 40,41 of M
        float f48 = (float)((nhi >> 8) & 1u);
        float f49 = (float)((nhi >> 9) & 1u);

        // threshold regs for current batch; rotate queue and prefetch ib+4
        float4 clo = q0lo, chi = q0hi;
        q0lo = q1lo; q0hi = q1hi; q1lo = q2lo; q1hi = q2hi; q2lo = q3lo; q2hi = q3hi;
        q3lo = *(const float4*)(g_th + ib * 8 + 32);
        q3hi = *(const float4*)(g_th + ib * 8 + 36);

        // ---- triangle: 8 steps, speculative lag-1 ----
        bool p0 = Bv0 > clo.x;
        float s0 = p0 ? 1.f : 0.f;
        float R1 = Bv1, R1G = R1 + G1;
        float x1 = p0 ? R1G : R1;
        bool p1 = x1 > clo.y;
        float s1 = p1 ? 1.f : 0.f;
        float R2 = fmaf(s0, Gv[2], Bv2), R2G = R2 + G1;
        float x2 = p1 ? R2G : R2;
        bool p2 = x2 > clo.z;
        float s2 = p2 ? 1.f : 0.f;
        float R3 = fmaf(s1, Gv[2], fmaf(s0, Gv[3], Bv3)), R3G = R3 + G1;
        float x3 = p2 ? R3G : R3;
        bool p3 = x3 > clo.w;
        float s3 = p3 ? 1.f : 0.f;
        float R4 = fmaf(s2, Gv[2], fmaf(s1, Gv[3], fmaf(s0, Gv[4], Bv4))), R4G = R4 + G1;
        float x4 = p3 ? R4G : R4;
        bool p4 = x4 > chi.x;
        float s4 = p4 ? 1.f : 0.f;
        float R5 = fmaf(s3, Gv[2], fmaf(s2, Gv[3], fmaf(s1, Gv[4], fmaf(s0, Gv[5], Bv5)))), R5G = R5 + G1;
        float x5 = p4 ? R5G : R5;
        bool p5 = x5 > chi.y;
        float s5 = p5 ? 1.f : 0.f;
        float R6 = fmaf(s4, Gv[2], fmaf(s3, Gv[3], fmaf(s2, Gv[4], fmaf(s1, Gv[5], fmaf(s0, Gv[6], Bv6))))), R6G = R6 + G1;
        float x6 = p5 ? R6G : R6;
        bool p6 = x6 > chi.z;
        float s6 = p6 ? 1.f : 0.f;
        float R7 = fmaf(s5, Gv[2], fmaf(s4, Gv[3], fmaf(s3, Gv[4], fmaf(s2, Gv[5], fmaf(s1, Gv[6], fmaf(s0, Gv[7], Bv7)))))), R7G = R7 + G1;
        float x7 = p6 ? R7G : R7;
        bool p7 = x7 > chi.w;

        unsigned fb = (unsigned)p0 | ((unsigned)p1 << 1) | ((unsigned)p2 << 2) | ((unsigned)p3 << 3)
                    | ((unsigned)p4 << 4) | ((unsigned)p5 << 5) | ((unsigned)p6 << 6) | ((unsigned)p7 << 7);
        unsigned rb = __brev(fb) >> 24;

        outw |= ((unsigned long long)fb) << (8 * (ib & 7));
        g_spk[ib >> 3] = outw;
        outw = ((ib & 7) == 7) ? 0ull : outw;

        // ---- post-stage: finish Bv for batch ib+1 ----
        M = (M << 8) | (unsigned long long)rb;
        ulonglong2 a0 = L[rb];
        ulonglong2 c0 = L[6 * 256 + rb];
        unsigned long long slo = f2add(f2add(f2add(a0.x, A1.x), PAx), QAx);
        unsigned long long shi = f2add(f2add(f2add(a0.y, A1.y), PAy), QAy);
        unsigned long long tlo = f2add(f2add(f2add(c0.x, C1.x), PCx), QCx);
        unsigned long long thi = f2add(f2add(f2add(c0.y, C1.y), PCy), QCy);
        Bv0 = fmaf(f49, G50, fmaf(f48, G49, lo32f(slo)));
        Bv1 = fmaf(f48, G50, hi32f(slo));
        Bv2 = lo32f(shi); Bv3 = hi32f(shi);
        Bv4 = lo32f(tlo); Bv5 = hi32f(tlo);
        Bv6 = lo32f(thi); Bv7 = hi32f(thi);
    }
}

// ---------------- K5: prob_out + spk_filt ----------------
__global__ void __launch_bounds__(256) k5_post(float* __restrict__ out) {
    __shared__ float sg[64], ss[64];
    int tid = threadIdx.x;
    if (tid < 64) { sg[tid] = g_g[tid]; ss[tid] = g_skd[tid]; }
    __syncthreads();
    int t = blockIdx.x * 256 + tid;
    if (t >= T_TOT) return;
    int w = t >> 6, off = t & 63;
    unsigned long long cur  = g_spk[w];
    unsigned long long prev = (w > 0) ? g_spk[w - 1] : 0ull;
    unsigned long long N = (off == 0) ? prev : ((cur << (64 - off)) | (prev >> off));
    float hist = 0.f, filt = 0.f;
    #pragma unroll
    for (int d = 1; d <= 50; d++) {
        float b = (N & (1ull << (64 - d))) ? 1.f : 0.f;
        hist = fmaf(b, sg[d], hist);
        filt = fmaf(b, ss[d], filt);
    }
    float z = g_out4[t] + hist + g_theta[0];
    float p = 1.f / (1.f + expf(-z));
    out[t] = filt;
    out[T_TOT + t] = p;
}

extern "C" void kernel_launch(void* const* d_in, const int* in_sizes, int n_in,
                              void* d_out, int out_size) {
    const float* Se  = (const float*)d_in[0];
    const float* Si  = (const float*)d_in[1];
    const float* Ce  = (const float*)d_in[2];
    const float* Ci  = (const float*)d_in[3];
    const float* w1  = (const float*)d_in[4];
    const float* w4  = (const float*)d_in[5];
    const float* Wh  = (const float*)d_in[6];
    const float* Th  = (const float*)d_in[7];
    const float* Ws  = (const float*)d_in[8];
    const float* Tau = (const float*)d_in[9];
    const float* u   = (const float*)d_in[10];
    float* out = (float*)d_out;

    k0_params<<<64, 256>>>(Ce, Ci, w1, w4, Wh, Th, Ws, Tau);
    k1_route<<<T_PAD / K1_TT, 256>>>(Se, Si);
    dim3 g2(T_PAD / 512, HIDN / 4);
    k2_conv1<<<g2, 128>>>();
    k3_conv4<<<782, 256>>>(u);
    k4_scan<<<1, 256>>>();
    k5_post<<<782, 256>>>(out);
}

// round 16
// speedup vs baseline: 1.6699x; 1.6699x over previous
#include <cuda_runtime.h>
#include <math.h>

#define T_TOT   200000
#define T_PAD   200704
#define PADL    64
#define SROW    (PADL + T_PAD + 64)
#define OROW    SROW
#define HIDN    20
#define SUBX2   40
#define NE      500
#define NI      100
#define KLEN    104
#define NBAS    34

__device__ float g_syn  [SUBX2 * SROW];
__device__ float g_out1 [HIDN  * OROW];
__device__ float g_kern1[HIDN * SUBX2 * KLEN];
__device__ float g_kern4[HIDN * KLEN];
__device__ float g_out4 [T_TOT];
__device__ float g_th   [200064];
__device__ float g_g    [64];
__device__ float g_skd  [64];
__device__ float g_theta[1];
__device__ int   g_idx_e[NE];
__device__ int   g_idx_i[NI];
__device__ unsigned long long g_spk[3200];
__device__ float g_sink [256];

__device__ __forceinline__ unsigned long long f2add(unsigned long long a, unsigned long long b) {
    unsigned long long c;
    asm("add.rn.f32x2 %0, %1, %2;" : "=l"(c) : "l"(a), "l"(b));
    return c;
}
__device__ __forceinline__ float lo32f(unsigned long long a) { return __uint_as_float((unsigned)a); }
__device__ __forceinline__ float hi32f(unsigned long long a) { return __uint_as_float((unsigned)(a >> 32)); }

// ---------------- K0: params ----------------
__global__ void k0_params(const float* __restrict__ Ce, const float* __restrict__ Ci,
                          const float* __restrict__ w1, const float* __restrict__ w4,
                          const float* __restrict__ Wh, const float* __restrict__ Th,
                          const float* __restrict__ Ws, const float* __restrict__ Tau) {
    __shared__ float sB[NBAS * KLEN];
    int tid = threadIdx.x;
    for (int i = tid; i < NBAS * KLEN; i += blockDim.x) {
        int b = i / KLEN, k = i % KLEN;
        float d = (float)k - 3.0f * (float)b;
        sB[i] = (k < 101) ? expf(-d * d / 3.0f) : 0.0f;
    }
    __syncthreads();
    int gt = blockIdx.x * blockDim.x + tid;
    int gs = gridDim.x * blockDim.x;

    for (int i = gt; i < HIDN * SUBX2 * KLEN; i += gs) {
        int k = i % KLEN, hs = i / KLEN;
        float acc = 0.f;
        if (k < 101) {
            const float* w = w1 + hs * NBAS;
            #pragma unroll
            for (int b = 0; b < NBAS; b++) acc = fmaf(w[b], sB[b * KLEN + k], acc);
        }
        g_kern1[i] = acc;
    }
    for (int i = gt; i < HIDN * KLEN; i += gs) {
        int k = i % KLEN, h = i / KLEN;
        float acc = 0.f;
        if (k < 101) {
            #pragma unroll
            for (int b = 0; b < NBAS; b++) acc = fmaf(w4[h * NBAS + b], sB[b * KLEN + k], acc);
        }
        g_kern4[i] = acc;
    }
    for (int d = gt; d < 64; d += gs) {
        float gv = 0.f, sv = 0.f;
        if (d >= 1 && d <= 50) {
            int kk = 50 - d;
            float a = 0.f;
            for (int i2 = 0; i2 < 18; i2++) {
                float dd = (float)kk - 3.0f * (float)i2;
                a = fmaf(Wh[i2], expf(-dd * dd / 3.0f), a);
            }
            gv = a;
            float tau2 = Tau[0] * Tau[0];
            float tt = (float)(d - 1) / tau2;
            sv = tt * expf(-tt) * Ws[0] * Ws[0];
        }
        g_g[d] = gv; g_skd[d] = sv;
    }
    if (gt == 0) g_theta[0] = Th[0];
    for (int e = gt; e < NE; e += gs) {
        int s = 0;
        for (int j = 0; j < 20; j++) if (Ce[j * NE + e] > 0.5f) s = j;
        g_idx_e[e] = s;
    }
    for (int e = gt; e < NI; e += gs) {
        int s = 0;
        for (int j = 0; j < 20; j++) if (Ci[j * NI + e] > 0.5f) s = j;
        g_idx_i[e] = 20 + s;
    }
    for (int i = gt; i < SUBX2 * PADL; i += gs) {
        int s = i / PADL, c = i % PADL;
        g_syn[s * SROW + c] = 0.f;
        g_syn[s * SROW + PADL + T_PAD + c] = 0.f;
    }
    for (int i = gt; i < HIDN * PADL; i += gs) {
        int h = i / PADL, c = i % PADL;
        g_out1[h * OROW + c] = 0.f;
        g_out1[h * OROW + PADL + T_PAD + c] = 0.f;
    }
}

// ---------------- K1: routing ----------------
#define K1_TT 128
__global__ void __launch_bounds__(256) k1_route(const float* __restrict__ Se,
                                                const float* __restrict__ Si) {
    __shared__ float acc[K1_TT][41];
    __shared__ int sIe[NE];
    __shared__ int sIi[NI];
    int tid = threadIdx.x;
    for (int i = tid; i < NE; i += 256) sIe[i] = g_idx_e[i];
    for (int i = tid; i < NI; i += 256) sIi[i] = g_idx_i[i];
    for (int i = tid; i < K1_TT * 41; i += 256) ((float*)acc)[i] = 0.f;
    __syncthreads();
    int t0 = blockIdx.x * K1_TT;
    for (int i = tid; i < K1_TT * NE; i += 256) {
        int tl = i / NE, e = i % NE;
        int t = t0 + tl;
        if (t < T_TOT) {
            float v = Se[(size_t)t * NE + e];
            if (v != 0.f) atomicAdd(&acc[tl][sIe[e]], v);
        }
    }
    for (int i = tid; i < K1_TT * NI; i += 256) {
        int tl = i / NI, e = i % NI;
        int t = t0 + tl;
        if (t < T_TOT) {
            float v = Si[(size_t)t * NI + e];
            if (v != 0.f) atomicAdd(&acc[tl][sIi[e]], v);
        }
    }
    __syncthreads();
    for (int i = tid; i < K1_TT * 40; i += 256) {
        int s = i / K1_TT, tl = i % K1_TT;
        g_syn[s * SROW + PADL + t0 + tl] = acc[tl][s];
    }
}

// ---------------- K2: conv1 + leaky relu ----------------
__global__ void __launch_bounds__(128) k2_conv1() {
    __shared__ __align__(16) float sSyn[8 * 616];
    __shared__ __align__(16) float sK[4 * 8 * KLEN];
    int tx  = threadIdx.x;
    int bT0 = blockIdx.x * 512;
    int hb  = blockIdx.y * 4;

    float acc[4][4];
    #pragma unroll
    for (int a = 0; a < 4; a++)
        #pragma unroll
        for (int b = 0; b < 4; b++) acc[a][b] = 0.f;

    #pragma unroll 1
    for (int sc = 0; sc < 5; sc++) {
        __syncthreads();
        for (int i = tx; i < 8 * 616; i += 128) {
            int ss = i / 616, c = i % 616;
            sSyn[i] = g_syn[(sc * 8 + ss) * SROW + PADL + bT0 - 50 + c];
        }
        for (int i = tx; i < 4 * 8 * KLEN; i += 128) {
            int hh = i / (8 * KLEN);
            int r = i % (8 * KLEN);
            int ss = r / KLEN, k = r % KLEN;
            sK[i] = g_kern1[((hb + hh) * SUBX2 + sc * 8 + ss) * KLEN + k];
        }
        __syncthreads();
        #pragma unroll 1
        for (int ss = 0; ss < 8; ss++) {
            const float* sp = sSyn + ss * 616 + 4 * tx;
            #pragma unroll
            for (int k4 = 0; k4 < 26; k4++) {
                float4 a = *(const float4*)(sp + 4 * k4);
                float4 b = *(const float4*)(sp + 4 * k4 + 4);
                #pragma unroll
                for (int hh = 0; hh < 4; hh++) {
                    float4 kv = *(const float4*)(sK + (hh * 8 + ss) * KLEN + 4 * k4);
                    acc[hh][0] = fmaf(a.x, kv.x, fmaf(a.y, kv.y, fmaf(a.z, kv.z, fmaf(a.w, kv.w, acc[hh][0]))));
                    acc[hh][1] = fmaf(a.y, kv.x, fmaf(a.z, kv.y, fmaf(a.w, kv.z, fmaf(b.x, kv.w, acc[hh][1]))));
                    acc[hh][2] = fmaf(a.z, kv.x, fmaf(a.w, kv.y, fmaf(b.x, kv.z, fmaf(b.y, kv.w, acc[hh][2]))));
                    acc[hh][3] = fmaf(a.w, kv.x, fmaf(b.x, kv.y, fmaf(b.y, kv.z, fmaf(b.z, kv.w, acc[hh][3]))));
                }
            }
        }
    }
    int gb = bT0 + 4 * tx;
    #pragma unroll
    for (int hh = 0; hh < 4; hh++)
        #pragma unroll
        for (int j = 0; j < 4; j++) {
            int t = gb + j;
            float v = acc[hh][j];
            v = v > 0.f ? v : 0.01f * v;
            g_out1[(hb + hh) * OROW + PADL + t] = (t < T_TOT) ? v : 0.f;
        }
}

// ---------------- K3: conv4 + thresholds ----------------
__global__ void __launch_bounds__(256) k3_conv4(const float* __restrict__ u) {
    __shared__ float s1[20 * 360];
    __shared__ float sk[20 * KLEN];
    int tx = threadIdx.x;
    int bT0 = blockIdx.x * 256;
    for (int i = tx; i < 20 * 360; i += 256) {
        int h = i / 360, c = i % 360;
        s1[i] = g_out1[h * OROW + PADL + bT0 - 50 + c];
    }
    for (int i = tx; i < 20 * KLEN; i += 256) sk[i] = g_kern4[i];
    __syncthreads();
    float acc0 = 0.f, acc1 = 0.f;
    #pragma unroll 1
    for (int h = 0; h < 20; h++) {
        const float* p  = s1 + h * 360 + tx;
        const float* kq = sk + h * KLEN;
        #pragma unroll
        for (int k = 0; k < 100; k += 2) {
            acc0 = fmaf(p[k],     kq[k],     acc0);
            acc1 = fmaf(p[k + 1], kq[k + 1], acc1);
        }
        acc0 = fmaf(p[100], kq[100], acc0);
    }
    float acc = acc0 + acc1;
    int t = bT0 + tx;
    if (t < T_TOT) {
        g_out4[t] = acc;
        float uu = u[t];
        g_th[t] = logf(uu / (1.f - uu)) - acc - g_theta[0];
    } else if (t < 200064) {
        g_th[t] = 1e30f;
    }
}

// ---------------- K4: sequential scan (branchless body + L2-warming warps) ----------------
__global__ void __launch_bounds__(256) k4_scan() {
    __shared__ __align__(16) float4 sLUT[12 * 256];   // 48 KB
    int tid = threadIdx.x;
    for (int idx = tid; idx < 12 * 256; idx += 256) {
        int grp = idx / (6 * 256);
        int rem = idx % (6 * 256);
        int B = rem / 256, v = rem % 256;
        float4 o = make_float4(0.f, 0.f, 0.f, 0.f);
        for (int i = 0; i < 8; i++)
            if (v & (1 << i)) {
                int d0 = 8 * B + i + 1 + 4 * grp;
                o.x += g_g[d0];
                o.y += g_g[d0 + 1];
                o.z += g_g[d0 + 2];
                o.w += g_g[d0 + 3];
            }
        sLUT[idx] = o;
    }
    __syncthreads();

    if (tid >= 32) {
        // L2-warming: 7 idle warps stream g_th through L2 ahead of the scan thread.
        int lane0 = tid - 32;                 // 0..223
        float4 acc4 = make_float4(0.f, 0.f, 0.f, 0.f);
        for (int i = lane0 * 4; i < 200064; i += 224 * 4) {
            float4 v = *(const float4*)(g_th + i);
            acc4.x += v.x; acc4.y += v.y; acc4.z += v.z; acc4.w += v.w;
        }
        g_sink[tid] = acc4.x + acc4.y + acc4.z + acc4.w;
        return;
    }
    if (tid != 0) return;

    float Gv[8];
    #pragma unroll
    for (int i = 0; i < 8; i++) Gv[i] = g_g[i];
    float G49 = g_g[49], G50 = g_g[50];

    unsigned long long M = 0ull, outw = 0ull;
    float4 q0lo = *(const float4*)(g_th + 0),  q0hi = *(const float4*)(g_th + 4);
    float4 q1lo = *(const float4*)(g_th + 8),  q1hi = *(const float4*)(g_th + 12);

    const ulonglong2* L = (const ulonglong2*)sLUT;

    for (int ib = 0; ib < 25000; ib++) {
        int tbase = ib * 8;
        float4 clo = q0lo, chi = q0hi;
        q0lo = q1lo; q0hi = q1hi;
        q1lo = *(const float4*)(g_th + tbase + 16);
        q1hi = *(const float4*)(g_th + tbase + 20);

        unsigned lo = (unsigned)M, hi = (unsigned)(M >> 32);
        int b0 = lo & 255, b1 = (lo >> 8) & 255, b2 = (lo >> 16) & 255, b3 = lo >> 24;
        int b4 = hi & 255, b5 = (hi >> 8) & 255;

        ulonglong2 a0 = L[0 * 256 + b0],   a1 = L[1 * 256 + b1];
        ulonglong2 a2 = L[2 * 256 + b2],   a3 = L[3 * 256 + b3];
        ulonglong2 a4 = L[4 * 256 + b4],   a5 = L[5 * 256 + b5];
        unsigned long long slo = f2add(f2add(f2add(a0.x, a1.x), f2add(a2.x, a3.x)), f2add(a4.x, a5.x));
        unsigned long long shi = f2add(f2add(f2add(a0.y, a1.y), f2add(a2.y, a3.y)), f2add(a4.y, a5.y));
        ulonglong2 c0 = L[(6 + 0) * 256 + b0], c1 = L[(6 + 1) * 256 + b1];
        ulonglong2 c2 = L[(6 + 2) * 256 + b2], c3 = L[(6 + 3) * 256 + b3];
        ulonglong2 c4 = L[(6 + 4) * 256 + b4], c5 = L[(6 + 5) * 256 + b5];
        unsigned long long tlo = f2add(f2add(f2add(c0.x, c1.x), f2add(c2.x, c3.x)), f2add(c4.x, c5.x));
        unsigned long long thi = f2add(f2add(f2add(c0.y, c1.y), f2add(c2.y, c3.y)), f2add(c4.y, c5.y));

        float Bv[8];
        Bv[0] = lo32f(slo); Bv[1] = hi32f(slo); Bv[2] = lo32f(shi); Bv[3] = hi32f(shi);
        Bv[4] = lo32f(tlo); Bv[5] = hi32f(tlo); Bv[6] = lo32f(thi); Bv[7] = hi32f(thi);

        float b48 = (float)((unsigned)(M >> 48) & 1u);
        float b49 = (float)((unsigned)(M >> 49) & 1u);
        Bv[0] = fmaf(b49, G50, fmaf(b48, G49, Bv[0]));
        Bv[1] = fmaf(b48, G50, Bv[1]);

        float thv[8] = {clo.x, clo.y, clo.z, clo.w, chi.x, chi.y, chi.z, chi.w};
        float s[8];
        unsigned fb = 0;
        #pragma unroll
        for (int r = 0; r < 8; r++) {
            float x = Bv[r];
            #pragma unroll
            for (int j = 0; j < r; j++) x = fmaf(s[j], Gv[r - j], x);
            bool f = x > thv[r];
            s[r] = f ? 1.f : 0.f;
            fb |= (unsigned)f << r;
        }
        unsigned rb = __brev(fb) >> 24;
        M = (M << 8) | (unsigned long long)rb;
        outw |= ((unsigned long long)fb) << (8 * (ib & 7));
        g_spk[ib >> 3] = outw;
        outw = ((ib & 7) == 7) ? 0ull : outw;
    }
}

// ---------------- K5: prob_out + spk_filt ----------------
__global__ void __launch_bounds__(256) k5_post(float* __restrict__ out) {
    __shared__ float sg[64], ss[64];
    int tid = threadIdx.x;
    if (tid < 64) { sg[tid] = g_g[tid]; ss[tid] = g_skd[tid]; }
    __syncthreads();
    int t = blockIdx.x * 256 + tid;
    if (t >= T_TOT) return;
    int w = t >> 6, off = t & 63;
    unsigned long long cur  = g_spk[w];
    unsigned long long prev = (w > 0) ? g_spk[w - 1] : 0ull;
    unsigned long long N = (off == 0) ? prev : ((cur << (64 - off)) | (prev >> off));
    float hist = 0.f, filt = 0.f;
    #pragma unroll
    for (int d = 1; d <= 50; d++) {
        float b = (N & (1ull << (64 - d))) ? 1.f : 0.f;
        hist = fmaf(b, sg[d], hist);
        filt = fmaf(b, ss[d], filt);
    }
    float z = g_out4[t] + hist + g_theta[0];
    float p = 1.f / (1.f + expf(-z));
    out[t] = filt;
    out[T_TOT + t] = p;
}

extern "C" void kernel_launch(void* const* d_in, const int* in_sizes, int n_in,
                              void* d_out, int out_size) {
    const float* Se  = (const float*)d_in[0];
    const float* Si  = (const float*)d_in[1];
    const float* Ce  = (const float*)d_in[2];
    const float* Ci  = (const float*)d_in[3];
    const float* w1  = (const float*)d_in[4];
    const float* w4  = (const float*)d_in[5];
    const float* Wh  = (const float*)d_in[6];
    const float* Th  = (const float*)d_in[7];
    const float* Ws  = (const float*)d_in[8];
    const float* Tau = (const float*)d_in[9];
    const float* u   = (const float*)d_in[10];
    float* out = (float*)d_out;

    k0_params<<<64, 256>>>(Ce, Ci, w1, w4, Wh, Th, Ws, Tau);
    k1_route<<<T_PAD / K1_TT, 256>>>(Se, Si);
    dim3 g2(T_PAD / 512, HIDN / 4);
    k2_conv1<<<g2, 128>>>();
    k3_conv4<<<782, 256>>>(u);
    k4_scan<<<1, 256>>>();
    k5_post<<<782, 256>>>(out);
}

// round 17
// speedup vs baseline: 1.8646x; 1.1166x over previous
#include <cuda_runtime.h>
#include <math.h>

#define T_TOT   200000
#define T_PAD   200704
#define PADL    64
#define SROW    (PADL + T_PAD + 64)
#define OROW    SROW
#define HIDN    20
#define SUBX2   40
#define NE      500
#define NI      100
#define KLEN    104
#define NBAS    34

__device__ float g_syn  [SUBX2 * SROW];
__device__ float g_out1 [HIDN  * OROW];
__device__ float g_kern1[HIDN * SUBX2 * KLEN];
__device__ float g_kern4[HIDN * KLEN];
__device__ float g_out4 [T_TOT];
__device__ float g_th   [200064];
__device__ float g_g    [64];
__device__ float g_skd  [64];
__device__ float g_theta[1];
__device__ int   g_idx_e[NE];
__device__ int   g_idx_i[NI];
__device__ unsigned long long g_spk[3200];
__device__ float g_sink [256];

__device__ __forceinline__ unsigned long long f2add(unsigned long long a, unsigned long long b) {
    unsigned long long c;
    asm("add.rn.f32x2 %0, %1, %2;" : "=l"(c) : "l"(a), "l"(b));
    return c;
}
__device__ __forceinline__ float lo32f(unsigned long long a) { return __uint_as_float((unsigned)a); }
__device__ __forceinline__ float hi32f(unsigned long long a) { return __uint_as_float((unsigned)(a >> 32)); }

// ---------------- K0: params ----------------
__global__ void k0_params(const float* __restrict__ Ce, const float* __restrict__ Ci,
                          const float* __restrict__ w1, const float* __restrict__ w4,
                          const float* __restrict__ Wh, const float* __restrict__ Th,
                          const float* __restrict__ Ws, const float* __restrict__ Tau) {
    __shared__ float sB[NBAS * KLEN];
    int tid = threadIdx.x;
    for (int i = tid; i < NBAS * KLEN; i += blockDim.x) {
        int b = i / KLEN, k = i % KLEN;
        float d = (float)k - 3.0f * (float)b;
        sB[i] = (k < 101) ? expf(-d * d / 3.0f) : 0.0f;
    }
    __syncthreads();
    int gt = blockIdx.x * blockDim.x + tid;
    int gs = gridDim.x * blockDim.x;

    for (int i = gt; i < HIDN * SUBX2 * KLEN; i += gs) {
        int k = i % KLEN, hs = i / KLEN;
        float acc = 0.f;
        if (k < 101) {
            const float* w = w1 + hs * NBAS;
            #pragma unroll
            for (int b = 0; b < NBAS; b++) acc = fmaf(w[b], sB[b * KLEN + k], acc);
        }
        g_kern1[i] = acc;
    }
    for (int i = gt; i < HIDN * KLEN; i += gs) {
        int k = i % KLEN, h = i / KLEN;
        float acc = 0.f;
        if (k < 101) {
            #pragma unroll
            for (int b = 0; b < NBAS; b++) acc = fmaf(w4[h * NBAS + b], sB[b * KLEN + k], acc);
        }
        g_kern4[i] = acc;
    }
    for (int d = gt; d < 64; d += gs) {
        float gv = 0.f, sv = 0.f;
        if (d >= 1 && d <= 50) {
            int kk = 50 - d;
            float a = 0.f;
            for (int i2 = 0; i2 < 18; i2++) {
                float dd = (float)kk - 3.0f * (float)i2;
                a = fmaf(Wh[i2], expf(-dd * dd / 3.0f), a);
            }
            gv = a;
            float tau2 = Tau[0] * Tau[0];
            float tt = (float)(d - 1) / tau2;
            sv = tt * expf(-tt) * Ws[0] * Ws[0];
        }
        g_g[d] = gv; g_skd[d] = sv;
    }
    if (gt == 0) g_theta[0] = Th[0];
    for (int e = gt; e < NE; e += gs) {
        int s = 0;
        for (int j = 0; j < 20; j++) if (Ce[j * NE + e] > 0.5f) s = j;
        g_idx_e[e] = s;
    }
    for (int e = gt; e < NI; e += gs) {
        int s = 0;
        for (int j = 0; j < 20; j++) if (Ci[j * NI + e] > 0.5f) s = j;
        g_idx_i[e] = 20 + s;
    }
    for (int i = gt; i < SUBX2 * PADL; i += gs) {
        int s = i / PADL, c = i % PADL;
        g_syn[s * SROW + c] = 0.f;
        g_syn[s * SROW + PADL + T_PAD + c] = 0.f;
    }
    for (int i = gt; i < HIDN * PADL; i += gs) {
        int h = i / PADL, c = i % PADL;
        g_out1[h * OROW + c] = 0.f;
        g_out1[h * OROW + PADL + T_PAD + c] = 0.f;
    }
}

// ---------------- K1: routing ----------------
#define K1_TT 128
__global__ void __launch_bounds__(256) k1_route(const float* __restrict__ Se,
                                                const float* __restrict__ Si) {
    __shared__ float acc[K1_TT][41];
    __shared__ int sIe[NE];
    __shared__ int sIi[NI];
    int tid = threadIdx.x;
    for (int i = tid; i < NE; i += 256) sIe[i] = g_idx_e[i];
    for (int i = tid; i < NI; i += 256) sIi[i] = g_idx_i[i];
    for (int i = tid; i < K1_TT * 41; i += 256) ((float*)acc)[i] = 0.f;
    __syncthreads();
    int t0 = blockIdx.x * K1_TT;
    for (int i = tid; i < K1_TT * NE; i += 256) {
        int tl = i / NE, e = i % NE;
        int t = t0 + tl;
        if (t < T_TOT) {
            float v = Se[(size_t)t * NE + e];
            if (v != 0.f) atomicAdd(&acc[tl][sIe[e]], v);
        }
    }
    for (int i = tid; i < K1_TT * NI; i += 256) {
        int tl = i / NI, e = i % NI;
        int t = t0 + tl;
        if (t < T_TOT) {
            float v = Si[(size_t)t * NI + e];
            if (v != 0.f) atomicAdd(&acc[tl][sIi[e]], v);
        }
    }
    __syncthreads();
    for (int i = tid; i < K1_TT * 40; i += 256) {
        int s = i / K1_TT, tl = i % K1_TT;
        g_syn[s * SROW + PADL + t0 + tl] = acc[tl][s];
    }
}

// ---------------- K2: conv1 + leaky relu ----------------
__global__ void __launch_bounds__(128) k2_conv1() {
    __shared__ __align__(16) float sSyn[8 * 616];
    __shared__ __align__(16) float sK[4 * 8 * KLEN];
    int tx  = threadIdx.x;
    int bT0 = blockIdx.x * 512;
    int hb  = blockIdx.y * 4;

    float acc[4][4];
    #pragma unroll
    for (int a = 0; a < 4; a++)
        #pragma unroll
        for (int b = 0; b < 4; b++) acc[a][b] = 0.f;

    #pragma unroll 1
    for (int sc = 0; sc < 5; sc++) {
        __syncthreads();
        for (int i = tx; i < 8 * 616; i += 128) {
            int ss = i / 616, c = i % 616;
            sSyn[i] = g_syn[(sc * 8 + ss) * SROW + PADL + bT0 - 50 + c];
        }
        for (int i = tx; i < 4 * 8 * KLEN; i += 128) {
            int hh = i / (8 * KLEN);
            int r = i % (8 * KLEN);
            int ss = r / KLEN, k = r % KLEN;
            sK[i] = g_kern1[((hb + hh) * SUBX2 + sc * 8 + ss) * KLEN + k];
        }
        __syncthreads();
        #pragma unroll 1
        for (int ss = 0; ss < 8; ss++) {
            const float* sp = sSyn + ss * 616 + 4 * tx;
            #pragma unroll
            for (int k4 = 0; k4 < 26; k4++) {
                float4 a = *(const float4*)(sp + 4 * k4);
                float4 b = *(const float4*)(sp + 4 * k4 + 4);
                #pragma unroll
                for (int hh = 0; hh < 4; hh++) {
                    float4 kv = *(const float4*)(sK + (hh * 8 + ss) * KLEN + 4 * k4);
                    acc[hh][0] = fmaf(a.x, kv.x, fmaf(a.y, kv.y, fmaf(a.z, kv.z, fmaf(a.w, kv.w, acc[hh][0]))));
                    acc[hh][1] = fmaf(a.y, kv.x, fmaf(a.z, kv.y, fmaf(a.w, kv.z, fmaf(b.x, kv.w, acc[hh][1]))));
                    acc[hh][2] = fmaf(a.z, kv.x, fmaf(a.w, kv.y, fmaf(b.x, kv.z, fmaf(b.y, kv.w, acc[hh][2]))));
                    acc[hh][3] = fmaf(a.w, kv.x, fmaf(b.x, kv.y, fmaf(b.y, kv.z, fmaf(b.z, kv.w, acc[hh][3]))));
                }
            }
        }
    }
    int gb = bT0 + 4 * tx;
    #pragma unroll
    for (int hh = 0; hh < 4; hh++)
        #pragma unroll
        for (int j = 0; j < 4; j++) {
            int t = gb + j;
            float v = acc[hh][j];
            v = v > 0.f ? v : 0.01f * v;
            g_out1[(hb + hh) * OROW + PADL + t] = (t < T_TOT) ? v : 0.f;
        }
}

// ---------------- K3: conv4 + thresholds ----------------
__global__ void __launch_bounds__(256) k3_conv4(const float* __restrict__ u) {
    __shared__ float s1[20 * 360];
    __shared__ float sk[20 * KLEN];
    int tx = threadIdx.x;
    int bT0 = blockIdx.x * 256;
    for (int i = tx; i < 20 * 360; i += 256) {
        int h = i / 360, c = i % 360;
        s1[i] = g_out1[h * OROW + PADL + bT0 - 50 + c];
    }
    for (int i = tx; i < 20 * KLEN; i += 256) sk[i] = g_kern4[i];
    __syncthreads();
    float acc0 = 0.f, acc1 = 0.f;
    #pragma unroll 1
    for (int h = 0; h < 20; h++) {
        const float* p  = s1 + h * 360 + tx;
        const float* kq = sk + h * KLEN;
        #pragma unroll
        for (int k = 0; k < 100; k += 2) {
            acc0 = fmaf(p[k],     kq[k],     acc0);
            acc1 = fmaf(p[k + 1], kq[k + 1], acc1);
        }
        acc0 = fmaf(p[100], kq[100], acc0);
    }
    float acc = acc0 + acc1;
    int t = bT0 + tx;
    if (t < T_TOT) {
        g_out4[t] = acc;
        float uu = u[t];
        g_th[t] = logf(uu / (1.f - uu)) - acc - g_theta[0];
    } else if (t < 200064) {
        g_th[t] = 1e30f;
    }
}

// ---------------- K4: sequential scan (unroll x8 + speculative lag-1 + L2 warm) ----------------
// Numerics bit-identical to the R16 kernel: same LUT, same tree order, same fixup
// order, and x_r = fmaf(s_{r-1},G1,R_r) realized as select(R_r+G1, R_r, p_{r-1}).
__global__ void __launch_bounds__(256) k4_scan() {
    __shared__ __align__(16) float4 sLUT[12 * 256];   // 48 KB
    int tid = threadIdx.x;
    for (int idx = tid; idx < 12 * 256; idx += 256) {
        int grp = idx / (6 * 256);
        int rem = idx % (6 * 256);
        int B = rem / 256, v = rem % 256;
        float4 o = make_float4(0.f, 0.f, 0.f, 0.f);
        for (int i = 0; i < 8; i++)
            if (v & (1 << i)) {
                int d0 = 8 * B + i + 1 + 4 * grp;
                o.x += g_g[d0];
                o.y += g_g[d0 + 1];
                o.z += g_g[d0 + 2];
                o.w += g_g[d0 + 3];
            }
        sLUT[idx] = o;
    }
    __syncthreads();

    if (tid >= 32) {
        // L2-warming: 7 idle warps stream g_th through L2 ahead of the scan thread.
        int lane0 = tid - 32;                 // 0..223
        float4 acc4 = make_float4(0.f, 0.f, 0.f, 0.f);
        for (int i = lane0 * 4; i < 200064; i += 224 * 4) {
            float4 v = *(const float4*)(g_th + i);
            acc4.x += v.x; acc4.y += v.y; acc4.z += v.z; acc4.w += v.w;
        }
        g_sink[tid] = acc4.x + acc4.y + acc4.z + acc4.w;
        return;
    }
    if (tid != 0) return;

    const float G1 = g_g[1], G2 = g_g[2], G3 = g_g[3], G4 = g_g[4];
    const float G5 = g_g[5], G6 = g_g[6], G7 = g_g[7];
    const float G49 = g_g[49], G50 = g_g[50];

    unsigned long long M = 0ull;
    float4 q0lo = *(const float4*)(g_th + 0),  q0hi = *(const float4*)(g_th + 4);
    float4 q1lo = *(const float4*)(g_th + 8),  q1hi = *(const float4*)(g_th + 12);

    const ulonglong2* L = (const ulonglong2*)sLUT;

    for (int ow = 0; ow < 3125; ow++) {
        unsigned long long outw = 0ull;
        #pragma unroll
        for (int sub = 0; sub < 8; sub++) {
            int ib = ow * 8 + sub;
            float4 clo = q0lo, chi = q0hi;
            q0lo = q1lo; q0hi = q1hi;
            q1lo = *(const float4*)(g_th + ib * 8 + 16);
            q1hi = *(const float4*)(g_th + ib * 8 + 20);

            unsigned lo = (unsigned)M, hi = (unsigned)(M >> 32);
            int b0 = lo & 255, b1 = (lo >> 8) & 255, b2 = (lo >> 16) & 255, b3 = lo >> 24;
            int b4 = hi & 255, b5 = (hi >> 8) & 255;

            ulonglong2 a0 = L[0 * 256 + b0],   a1 = L[1 * 256 + b1];
            ulonglong2 a2 = L[2 * 256 + b2],   a3 = L[3 * 256 + b3];
            ulonglong2 a4 = L[4 * 256 + b4],   a5 = L[5 * 256 + b5];
            unsigned long long slo = f2add(f2add(f2add(a0.x, a1.x), f2add(a2.x, a3.x)), f2add(a4.x, a5.x));
            unsigned long long shi = f2add(f2add(f2add(a0.y, a1.y), f2add(a2.y, a3.y)), f2add(a4.y, a5.y));
            ulonglong2 c0 = L[(6 + 0) * 256 + b0], c1 = L[(6 + 1) * 256 + b1];
            ulonglong2 c2 = L[(6 + 2) * 256 + b2], c3 = L[(6 + 3) * 256 + b3];
            ulonglong2 c4 = L[(6 + 4) * 256 + b4], c5 = L[(6 + 5) * 256 + b5];
            unsigned long long tlo = f2add(f2add(f2add(c0.x, c1.x), f2add(c2.x, c3.x)), f2add(c4.x, c5.x));
            unsigned long long thi = f2add(f2add(f2add(c0.y, c1.y), f2add(c2.y, c3.y)), f2add(c4.y, c5.y));

            float b48 = (float)((unsigned)(M >> 48) & 1u);
            float b49 = (float)((unsigned)(M >> 49) & 1u);
            float Bv0 = fmaf(b49, G50, fmaf(b48, G49, lo32f(slo)));
            float Bv1 = fmaf(b48, G50, hi32f(slo));
            float Bv2 = lo32f(shi), Bv3 = hi32f(shi);
            float Bv4 = lo32f(tlo), Bv5 = hi32f(tlo);
            float Bv6 = lo32f(thi), Bv7 = hi32f(thi);

            // triangle: speculative lag-1 (bit-exact vs fmaf(s_{r-1},G1,R))
            bool p0 = Bv0 > clo.x;
            float s0 = p0 ? 1.f : 0.f;
            float R1 = Bv1, R1G = R1 + G1;
            float x1 = p0 ? R1G : R1;
            bool p1 = x1 > clo.y;
            float s1 = p1 ? 1.f : 0.f;
            float R2 = fmaf(s0, G2, Bv2), R2G = R2 + G1;
            float x2 = p1 ? R2G : R2;
            bool p2 = x2 > clo.z;
            float s2 = p2 ? 1.f : 0.f;
            float R3 = fmaf(s1, G2, fmaf(s0, G3, Bv3)), R3G = R3 + G1;
            float x3 = p2 ? R3G : R3;
            bool p3 = x3 > clo.w;
            float s3 = p3 ? 1.f : 0.f;
            float R4 = fmaf(s2, G2, fmaf(s1, G3, fmaf(s0, G4, Bv4))), R4G = R4 + G1;
            float x4 = p3 ? R4G : R4;
            bool p4 = x4 > chi.x;
            float s4 = p4 ? 1.f : 0.f;
            float R5 = fmaf(s3, G2, fmaf(s2, G3, fmaf(s1, G4, fmaf(s0, G5, Bv5)))), R5G = R5 + G1;
            float x5 = p4 ? R5G : R5;
            bool p5 = x5 > chi.y;
            float s5 = p5 ? 1.f : 0.f;
            float R6 = fmaf(s4, G2, fmaf(s3, G3, fmaf(s2, G4, fmaf(s1, G5, fmaf(s0, G6, Bv6))))), R6G = R6 + G1;
            float x6 = p5 ? R6G : R6;
            bool p6 = x6 > chi.z;
            float s6 = p6 ? 1.f : 0.f;
            float R7 = fmaf(s5, G2, fmaf(s4, G3, fmaf(s3, G4, fmaf(s2, G5, fmaf(s1, G6, fmaf(s0, G7, Bv7)))))), R7G = R7 + G1;
            float x7 = p6 ? R7G : R7;
            bool p7 = x7 > chi.w;

            unsigned fb = (unsigned)p0 | ((unsigned)p1 << 1) | ((unsigned)p2 << 2) | ((unsigned)p3 << 3)
                        | ((unsigned)p4 << 4) | ((unsigned)p5 << 5) | ((unsigned)p6 << 6) | ((unsigned)p7 << 7);
            unsigned rb = __brev(fb) >> 24;
            M = (M << 8) | (unsigned long long)rb;
            outw |= ((unsigned long long)fb) << (8 * sub);
        }
        g_spk[ow] = outw;
    }
}

// ---------------- K5: prob_out + spk_filt ----------------
__global__ void __launch_bounds__(256) k5_post(float* __restrict__ out) {
    __shared__ float sg[64], ss[64];
    int tid = threadIdx.x;
    if (tid < 64) { sg[tid] = g_g[tid]; ss[tid] = g_skd[tid]; }
    __syncthreads();
    int t = blockIdx.x * 256 + tid;
    if (t >= T_TOT) return;
    int w = t >> 6, off = t & 63;
    unsigned long long cur  = g_spk[w];
    unsigned long long prev = (w > 0) ? g_spk[w - 1] : 0ull;
    unsigned long long N = (off == 0) ? prev : ((cur << (64 - off)) | (prev >> off));
    float hist = 0.f, filt = 0.f;
    #pragma unroll
    for (int d = 1; d <= 50; d++) {
        float b = (N & (1ull << (64 - d))) ? 1.f : 0.f;
        hist = fmaf(b, sg[d], hist);
        filt = fmaf(b, ss[d], filt);
    }
    float z = g_out4[t] + hist + g_theta[0];
    float p = 1.f / (1.f + expf(-z));
    out[t] = filt;
    out[T_TOT + t] = p;
}

extern "C" void kernel_launch(void* const* d_in, const int* in_sizes, int n_in,
                              void* d_out, int out_size) {
    const float* Se  = (const float*)d_in[0];
    const float* Si  = (const float*)d_in[1];
    const float* Ce  = (const float*)d_in[2];
    const float* Ci  = (const float*)d_in[3];
    const float* w1  = (const float*)d_in[4];
    const float* w4  = (const float*)d_in[5];
    const float* Wh  = (const float*)d_in[6];
    const float* Th  = (const float*)d_in[7];
    const float* Ws  = (const float*)d_in[8];
    const float* Tau = (const float*)d_in[9];
    const float* u   = (const float*)d_in[10];
    float* out = (float*)d_out;

    k0_params<<<64, 256>>>(Ce, Ci, w1, w4, Wh, Th, Ws, Tau);
    k1_route<<<T_PAD / K1_TT, 256>>>(Se, Si);
    dim3 g2(T_PAD / 512, HIDN / 4);
    k2_conv1<<<g2, 128>>>();
    k3_conv4<<<782, 256>>>(u);
    k4_scan<<<1, 256>>>();
    k5_post<<<782, 256>>>(out);
}